// round 13
// baseline (speedup 1.0000x reference)
#include <cuda_runtime.h>
#include <cuda_bf16.h>
#include <stdint.h>

#define NITEMS 512
#define MAXM   256
#define DIM    128
#define RPI    512
#define MAXPAIRS 131072
#define TM     64
#define PITCHB 528           // smem row pitch in bytes (264 bf16)
#define XBYTES 33792         // 64 * 528

__device__ __nv_bfloat16  g_bufh [(long)NITEMS * RPI * DIM];
__device__ __nv_bfloat16  g_bufl [(long)NITEMS * RPI * DIM];
// Weight images pre-packed in mma.m16n8k16 B-fragment order:
// [kstep][ntile][lane] -> uint2 (reg b0, reg b1)
__device__ uint2 g_W1hi[16 * 32 * 32];
__device__ uint2 g_W1lo[16 * 32 * 32];
__device__ uint2 g_W2hi[16 * 16 * 32];
__device__ uint2 g_W2lo[16 * 16 * 32];
__device__ int g_src[MAXPAIRS];
__device__ int g_dst[MAXPAIRS];
__device__ int g_off[4 * NITEMS];
__device__ int g_count[4];
__device__ int g_base[4];

__device__ __forceinline__ int get_limit(const int* lim, bool is64, int i) {
    return is64 ? lim[2 * i] : lim[i];
}
__device__ __forceinline__ void split2(float v, unsigned short& h, unsigned short& l) {
    __nv_bfloat16 hb = __float2bfloat16(v);
    __nv_bfloat16 lb = __float2bfloat16(v - __bfloat162float(hb));
    h = __bfloat16_as_ushort(hb); l = __bfloat16_as_ushort(lb);
}
__device__ __forceinline__ uint32_t pk(unsigned short a, unsigned short b) {
    return (uint32_t)a | ((uint32_t)b << 16);
}
__device__ __forceinline__ uint32_t smem_u32(const void* p) {
    uint32_t a;
    asm("{ .reg .u64 t; cvta.to.shared.u64 t, %1; cvt.u32.u64 %0, t; }" : "=r"(a) : "l"(p));
    return a;
}
__device__ __forceinline__ void ldm4(uint32_t* a, uint32_t addr) {
    asm volatile("ldmatrix.sync.aligned.m8n8.x4.shared.b16 {%0,%1,%2,%3}, [%4];"
                 : "=r"(a[0]), "=r"(a[1]), "=r"(a[2]), "=r"(a[3]) : "r"(addr));
}
__device__ __forceinline__ void mma16816(float* c, const uint32_t* a, uint2 b) {
    asm volatile(
        "mma.sync.aligned.m16n8k16.row.col.f32.bf16.bf16.f32 "
        "{%0,%1,%2,%3}, {%4,%5,%6,%7}, {%8,%9}, {%0,%1,%2,%3};"
        : "+f"(c[0]), "+f"(c[1]), "+f"(c[2]), "+f"(c[3])
        : "r"(a[0]), "r"(a[1]), "r"(a[2]), "r"(a[3]), "r"(b.x), "r"(b.y));
}

// ---------------------------------------------------------------------------
__global__ void k_scatter(const float* __restrict__ args, const int* __restrict__ lim) {
    int item = blockIdx.y;
    bool is64 = (lim[1] == 0);
    int start = get_limit(lim, is64, item);
    int L     = get_limit(lim, is64, item + 1) - start;
    int r0 = blockIdx.x * 64;
    int nrows = min(64, L - r0);
    if (nrows <= 0) return;
    const float4* src = (const float4*)(args + (long)(start + r0) * DIM);
    uint2* dh = (uint2*)(g_bufh + ((long)item * RPI + r0) * DIM);
    uint2* dl = (uint2*)(g_bufl + ((long)item * RPI + r0) * DIM);
    int total = nrows * (DIM / 4);
    for (int i = threadIdx.x; i < total; i += blockDim.x) {
        float4 x = src[i];
        unsigned short h0, l0, h1, l1, h2, l2, h3, l3;
        split2(x.x, h0, l0); split2(x.y, h1, l1);
        split2(x.z, h2, l2); split2(x.w, h3, l3);
        dh[i] = make_uint2(pk(h0, h1), pk(h2, h3));
        dl[i] = make_uint2(pk(l0, l1), pk(l2, l3));
    }
}

// ---------------------------------------------------------------------------
__global__ void k_scan(const int* __restrict__ lim) {
    __shared__ int sc[NITEMS];
    int i = threadIdx.x;
    bool is64 = (lim[1] == 0);
    int L = get_limit(lim, is64, i + 1) - get_limit(lim, is64, i);
    int l = L, base = 0;
    for (int k = 0; k < 4; k++) {
        int pr = l >> 1;
        sc[i] = pr;
        __syncthreads();
        for (int off = 1; off < NITEMS; off <<= 1) {
            int v = sc[i];
            int w = (i >= off) ? sc[i - off] : 0;
            __syncthreads();
            sc[i] = v + w;
            __syncthreads();
        }
        g_off[k * NITEMS + i] = sc[i] - pr;
        if (i == 0) { g_count[k] = sc[NITEMS - 1]; g_base[k] = base; }
        base += sc[NITEMS - 1];
        l = (l + 1) >> 1;
        __syncthreads();
    }
}

// ---------------------------------------------------------------------------
__global__ void k_fillw(const int* __restrict__ lim,
                        const float* __restrict__ W1, const float* __restrict__ W2) {
    if (blockIdx.x < 64) {
        int g = blockIdx.x * 256 + threadIdx.x;        // [0, 16384)
        int kstep = g >> 10, ntile = (g >> 5) & 31, lane = g & 31;
        int kb = kstep * 16 + (lane & 3) * 2;
        {
            int n = ntile * 8 + (lane >> 2);
            unsigned short h00, l00, h01, l01, h10, l10, h11, l11;
            split2(W1[kb * 256 + n],       h00, l00);
            split2(W1[(kb + 1) * 256 + n], h01, l01);
            split2(W1[(kb + 8) * 256 + n], h10, l10);
            split2(W1[(kb + 9) * 256 + n], h11, l11);
            int idx = (kstep * 32 + ntile) * 32 + lane;
            g_W1hi[idx] = make_uint2(pk(h00, h01), pk(h10, h11));
            g_W1lo[idx] = make_uint2(pk(l00, l01), pk(l10, l11));
        }
        if (ntile < 16) {
            int n = ntile * 8 + (lane >> 2);
            unsigned short h00, l00, h01, l01, h10, l10, h11, l11;
            split2(W2[kb * 128 + n],       h00, l00);
            split2(W2[(kb + 1) * 128 + n], h01, l01);
            split2(W2[(kb + 8) * 128 + n], h10, l10);
            split2(W2[(kb + 9) * 128 + n], h11, l11);
            int idx = (kstep * 16 + ntile) * 32 + lane;
            g_W2hi[idx] = make_uint2(pk(h00, h01), pk(h10, h11));
            g_W2lo[idx] = make_uint2(pk(l00, l01), pk(l10, l11));
        }
    }
    int item = blockIdx.x;
    bool is64 = (lim[1] == 0);
    int L = get_limit(lim, is64, item + 1) - get_limit(lim, is64, item);
    int s = 0, l = L;
    int rowb = item * RPI;
    for (int k = 0; k < 4; k++) {
        int pr = l >> 1;
        int e = g_base[k] + g_off[k * NITEMS + item];
        for (int p = threadIdx.x; p < pr; p += blockDim.x) {
            g_src[e + p] = rowb + s + 2 * p;
            g_dst[e + p] = rowb + s + l + p;
        }
        s += 2 * pr;
        l = (l + 1) >> 1;
    }
}

// ---------------------------------------------------------------------------
// Batched level kernel (levels 0..3): 64 pairs/CTA, 8 warps (2 M x 4 N).
// Term-major mma ordering: preload bh[8]/bl[8], then 3 passes of 16
// INDEPENDENT mma (acc reuse distance 16) -> no HMMA RAW stalls.
// ---------------------------------------------------------------------------
extern __shared__ __align__(16) unsigned char smraw[];

__global__ void __launch_bounds__(256, 2) k_level_mma(
    const float* __restrict__ b1, const float* __restrict__ b2,
    const float* __restrict__ lnw, const float* __restrict__ lnb, int level)
{
    int cnt = g_count[level], base = g_base[level];
    int j0 = blockIdx.x * TM;
    if (j0 >= cnt) return;
    int np = min(TM, cnt - j0);

    unsigned char* Xhi = smraw;
    unsigned char* Xlo = smraw + XBYTES;
    uint32_t XhiA = smem_u32(Xhi);
    uint32_t XloA = XhiA + XBYTES;

    int tid = threadIdx.x;
    int warp = tid >> 5, lane = tid & 31;
    int warp_m = warp & 1, warp_n = warp >> 1;

    {
        const uint4* sh = (const uint4*)g_bufh;
        const uint4* sl = (const uint4*)g_bufl;
        #pragma unroll
        for (int it = 0; it < 8; it++) {
            int f = it * 256 + tid;
            int r = f >> 5, q = f & 31;
            int rc = min(r, np - 1);
            int sr = g_src[base + j0 + rc];
            *(uint4*)(Xhi + r * PITCHB + q * 16) = sh[(long)sr * 16 + q];
            *(uint4*)(Xlo + r * PITCHB + q * 16) = sl[(long)sr * 16 + q];
        }
    }
    __syncthreads();

    int lrow = lane & 15;
    int lcol = (lane >> 4) << 3;
    uint32_t rowA0 = (uint32_t)(warp_m * 32 + lrow) * PITCHB;
    uint32_t rowA1 = (uint32_t)(warp_m * 32 + 16 + lrow) * PITCHB;

    // ---- GEMM1: term-major fused 3-term ----
    float acc[2][8][4];
    #pragma unroll
    for (int rb = 0; rb < 2; rb++)
        #pragma unroll
        for (int nt = 0; nt < 8; nt++)
            #pragma unroll
            for (int e = 0; e < 4; e++) acc[rb][nt][e] = 0.f;

    #pragma unroll 1
    for (int ks = 0; ks < 16; ks++) {
        uint32_t col2 = (uint32_t)(ks * 16 + lcol) * 2;
        uint32_t ah0[4], ah1[4], al0[4], al1[4];
        ldm4(ah0, XhiA + rowA0 + col2);
        ldm4(ah1, XhiA + rowA1 + col2);
        ldm4(al0, XloA + rowA0 + col2);
        ldm4(al1, XloA + rowA1 + col2);
        uint2 bh[8], bl[8];
        #pragma unroll
        for (int nt = 0; nt < 8; nt++) {
            int bi = (ks * 32 + warp_n * 8 + nt) * 32 + lane;
            bh[nt] = g_W1hi[bi];
            bl[nt] = g_W1lo[bi];
        }
        #pragma unroll
        for (int nt = 0; nt < 8; nt++) {
            mma16816(acc[0][nt], ah0, bh[nt]);
            mma16816(acc[1][nt], ah1, bh[nt]);
        }
        #pragma unroll
        for (int nt = 0; nt < 8; nt++) {
            mma16816(acc[0][nt], ah0, bl[nt]);
            mma16816(acc[1][nt], ah1, bl[nt]);
        }
        #pragma unroll
        for (int nt = 0; nt < 8; nt++) {
            mma16816(acc[0][nt], al0, bh[nt]);
            mma16816(acc[1][nt], al1, bh[nt]);
        }
    }
    __syncthreads();

    // ---- Epilogue1: H = relu(acc + b1) -> X images ----
    #pragma unroll
    for (int rb = 0; rb < 2; rb++) {
        int row = warp_m * 32 + rb * 16 + (lane >> 2);
        #pragma unroll
        for (int nt = 0; nt < 8; nt++) {
            int col = (warp_n * 8 + nt) * 8 + (lane & 3) * 2;
            float v0 = fmaxf(acc[rb][nt][0] + b1[col], 0.f);
            float v1 = fmaxf(acc[rb][nt][1] + b1[col + 1], 0.f);
            float v2 = fmaxf(acc[rb][nt][2] + b1[col], 0.f);
            float v3 = fmaxf(acc[rb][nt][3] + b1[col + 1], 0.f);
            unsigned short h0, l0, h1, l1, h2, l2, h3, l3;
            split2(v0, h0, l0); split2(v1, h1, l1);
            split2(v2, h2, l2); split2(v3, h3, l3);
            *(uint32_t*)(Xhi + row * PITCHB + col * 2)       = pk(h0, h1);
            *(uint32_t*)(Xlo + row * PITCHB + col * 2)       = pk(l0, l1);
            *(uint32_t*)(Xhi + (row + 8) * PITCHB + col * 2) = pk(h2, h3);
            *(uint32_t*)(Xlo + (row + 8) * PITCHB + col * 2) = pk(l2, l3);
        }
    }
    __syncthreads();

    // ---- GEMM2: term-major fused 3-term ----
    float acc2[2][4][4];
    #pragma unroll
    for (int rb = 0; rb < 2; rb++)
        #pragma unroll
        for (int nt = 0; nt < 4; nt++)
            #pragma unroll
            for (int e = 0; e < 4; e++) acc2[rb][nt][e] = 0.f;

    #pragma unroll 1
    for (int ks = 0; ks < 16; ks++) {
        uint32_t col2 = (uint32_t)(ks * 16 + lcol) * 2;
        uint32_t ah0[4], ah1[4], al0[4], al1[4];
        ldm4(ah0, XhiA + rowA0 + col2);
        ldm4(ah1, XhiA + rowA1 + col2);
        ldm4(al0, XloA + rowA0 + col2);
        ldm4(al1, XloA + rowA1 + col2);
        uint2 bh[4], bl[4];
        #pragma unroll
        for (int nt = 0; nt < 4; nt++) {
            int bi = (ks * 16 + warp_n * 4 + nt) * 32 + lane;
            bh[nt] = g_W2hi[bi];
            bl[nt] = g_W2lo[bi];
        }
        #pragma unroll
        for (int nt = 0; nt < 4; nt++) {
            mma16816(acc2[0][nt], ah0, bh[nt]);
            mma16816(acc2[1][nt], ah1, bh[nt]);
        }
        #pragma unroll
        for (int nt = 0; nt < 4; nt++) {
            mma16816(acc2[0][nt], ah0, bl[nt]);
            mma16816(acc2[1][nt], ah1, bl[nt]);
        }
        #pragma unroll
        for (int nt = 0; nt < 4; nt++) {
            mma16816(acc2[0][nt], al0, bh[nt]);
            mma16816(acc2[1][nt], al1, bh[nt]);
        }
    }
    __syncthreads();

    // ---- Epilogue2a: Y -> f32 smem [64][132] ----
    float* Ys = (float*)Xhi;
    #pragma unroll
    for (int rb = 0; rb < 2; rb++) {
        int row = warp_m * 32 + rb * 16 + (lane >> 2);
        #pragma unroll
        for (int nt = 0; nt < 4; nt++) {
            int col = (warp_n * 4 + nt) * 8 + (lane & 3) * 2;
            *(float2*)(Ys + row * 132 + col) =
                make_float2(acc2[rb][nt][0] + b2[col], acc2[rb][nt][1] + b2[col + 1]);
            *(float2*)(Ys + (row + 8) * 132 + col) =
                make_float2(acc2[rb][nt][2] + b2[col], acc2[rb][nt][3] + b2[col + 1]);
        }
    }
    __syncthreads();

    // ---- Epilogue2b: LayerNorm + store hi/lo ----
    #pragma unroll
    for (int rr = 0; rr < 8; rr++) {
        int row = warp * 8 + rr;
        int d = (row < np) ? g_dst[base + j0 + row] : -1;
        float4 y = *(const float4*)(Ys + row * 132 + lane * 4);
        float sum = y.x + y.y + y.z + y.w;
        float sq  = y.x * y.x + y.y * y.y + y.z * y.z + y.w * y.w;
        #pragma unroll
        for (int o = 16; o > 0; o >>= 1) {
            sum += __shfl_xor_sync(0xFFFFFFFFu, sum, o);
            sq  += __shfl_xor_sync(0xFFFFFFFFu, sq, o);
        }
        float mu  = sum * (1.f / 128.f);
        float var = sq * (1.f / 128.f) - mu * mu;
        float rs  = rsqrtf(var + 1e-5f);
        float4 wv = ((const float4*)lnw)[lane];
        float4 bv = ((const float4*)lnb)[lane];
        float4 o;
        o.x = (y.x - mu) * rs * wv.x + bv.x;
        o.y = (y.y - mu) * rs * wv.y + bv.y;
        o.z = (y.z - mu) * rs * wv.z + bv.z;
        o.w = (y.w - mu) * rs * wv.w + bv.w;
        if (d >= 0) {
            unsigned short h0, l0, h1, l1, h2, l2, h3, l3;
            split2(o.x, h0, l0); split2(o.y, h1, l1);
            split2(o.z, h2, l2); split2(o.w, h3, l3);
            ((uint2*)g_bufh)[(long)d * 32 + lane] = make_uint2(pk(h0, h1), pk(h2, h3));
            ((uint2*)g_bufl)[(long)d * 32 + lane] = make_uint2(pk(l0, l1), pk(l2, l3));
        }
    }
}

// ---------------------------------------------------------------------------
// Finisher: one CTA per item, levels 4..7 + fused gather. Term-major order.
// ---------------------------------------------------------------------------
__global__ void __launch_bounds__(256, 4) k_finish(
    const float* __restrict__ b1, const float* __restrict__ b2,
    const float* __restrict__ lnw, const float* __restrict__ lnb,
    const int* __restrict__ lim, float* __restrict__ out)
{
    __shared__ __align__(16) unsigned char Xhi[16 * PITCHB];   // 8448 B
    __shared__ __align__(16) unsigned char Xlo[16 * PITCHB];

    int item = blockIdx.x;
    bool is64 = (lim[1] == 0);
    int L = get_limit(lim, is64, item + 1) - get_limit(lim, is64, item);
    int s = 0, l = L;
    #pragma unroll
    for (int t = 0; t < 4; t++) { int pr = l >> 1; s += 2 * pr; l = (l + 1) >> 1; }
    int rowb = item * RPI;

    uint32_t XhiA = smem_u32(Xhi);
    uint32_t XloA = smem_u32(Xlo);
    int tid = threadIdx.x;
    int warp = tid >> 5, lane = tid & 31;
    int lrow = lane & 15;
    int lcol = (lane >> 4) << 3;
    uint32_t rowA = (uint32_t)lrow * PITCHB;

    #pragma unroll 1
    for (int lev = 0; lev < 4 && l >= 2; lev++) {
        int pairs = l >> 1;    // 1..8

        {
            const uint4* sh = (const uint4*)g_bufh;
            const uint4* sl = (const uint4*)g_bufl;
            int tot = pairs * 32;
            for (int f = tid; f < tot; f += 256) {
                int r = f >> 5, q = f & 31;
                long gsrc = (long)(rowb + s + 2 * r) * 16 + q;
                *(uint4*)(Xhi + r * PITCHB + q * 16) = sh[gsrc];
                *(uint4*)(Xlo + r * PITCHB + q * 16) = sl[gsrc];
            }
        }
        __syncthreads();

        // GEMM1: warp tile 16 x 32, term-major
        float acc[4][4];
        #pragma unroll
        for (int nt = 0; nt < 4; nt++)
            #pragma unroll
            for (int e = 0; e < 4; e++) acc[nt][e] = 0.f;
        #pragma unroll 1
        for (int ks = 0; ks < 16; ks++) {
            uint32_t col2 = (uint32_t)(ks * 16 + lcol) * 2;
            uint32_t ah[4], al[4];
            ldm4(ah, XhiA + rowA + col2);
            ldm4(al, XloA + rowA + col2);
            uint2 bh[4], bl[4];
            #pragma unroll
            for (int nt = 0; nt < 4; nt++) {
                int bi = (ks * 32 + warp * 4 + nt) * 32 + lane;
                bh[nt] = g_W1hi[bi];
                bl[nt] = g_W1lo[bi];
            }
            #pragma unroll
            for (int nt = 0; nt < 4; nt++) mma16816(acc[nt], ah, bh[nt]);
            #pragma unroll
            for (int nt = 0; nt < 4; nt++) mma16816(acc[nt], ah, bl[nt]);
            #pragma unroll
            for (int nt = 0; nt < 4; nt++) mma16816(acc[nt], al, bh[nt]);
        }
        __syncthreads();

        {
            int row = lane >> 2;
            #pragma unroll
            for (int nt = 0; nt < 4; nt++) {
                int col = (warp * 4 + nt) * 8 + (lane & 3) * 2;
                float v0 = fmaxf(acc[nt][0] + b1[col], 0.f);
                float v1 = fmaxf(acc[nt][1] + b1[col + 1], 0.f);
                float v2 = fmaxf(acc[nt][2] + b1[col], 0.f);
                float v3 = fmaxf(acc[nt][3] + b1[col + 1], 0.f);
                unsigned short h0, l0_, h1, l1_, h2, l2_, h3, l3_;
                split2(v0, h0, l0_); split2(v1, h1, l1_);
                split2(v2, h2, l2_); split2(v3, h3, l3_);
                *(uint32_t*)(Xhi + row * PITCHB + col * 2)       = pk(h0, h1);
                *(uint32_t*)(Xlo + row * PITCHB + col * 2)       = pk(l0_, l1_);
                *(uint32_t*)(Xhi + (row + 8) * PITCHB + col * 2) = pk(h2, h3);
                *(uint32_t*)(Xlo + (row + 8) * PITCHB + col * 2) = pk(l2_, l3_);
            }
        }
        __syncthreads();

        // GEMM2: warp tile 16 x 16, term-major
        float acc2[2][4];
        #pragma unroll
        for (int nt = 0; nt < 2; nt++)
            #pragma unroll
            for (int e = 0; e < 4; e++) acc2[nt][e] = 0.f;
        #pragma unroll 1
        for (int ks = 0; ks < 16; ks++) {
            uint32_t col2 = (uint32_t)(ks * 16 + lcol) * 2;
            uint32_t ah[4], al[4];
            ldm4(ah, XhiA + rowA + col2);
            ldm4(al, XloA + rowA + col2);
            uint2 bh[2], bl[2];
            #pragma unroll
            for (int nt = 0; nt < 2; nt++) {
                int bi = (ks * 16 + warp * 2 + nt) * 32 + lane;
                bh[nt] = g_W2hi[bi];
                bl[nt] = g_W2lo[bi];
            }
            #pragma unroll
            for (int nt = 0; nt < 2; nt++) mma16816(acc2[nt], ah, bh[nt]);
            #pragma unroll
            for (int nt = 0; nt < 2; nt++) mma16816(acc2[nt], ah, bl[nt]);
            #pragma unroll
            for (int nt = 0; nt < 2; nt++) mma16816(acc2[nt], al, bh[nt]);
        }
        __syncthreads();

        float* Ys = (float*)Xhi;
        {
            int row = lane >> 2;
            #pragma unroll
            for (int nt = 0; nt < 2; nt++) {
                int col = (warp * 2 + nt) * 8 + (lane & 3) * 2;
                *(float2*)(Ys + row * 132 + col) =
                    make_float2(acc2[nt][0] + b2[col], acc2[nt][1] + b2[col + 1]);
                *(float2*)(Ys + (row + 8) * 132 + col) =
                    make_float2(acc2[nt][2] + b2[col], acc2[nt][3] + b2[col + 1]);
            }
        }
        __syncthreads();

        if (warp < pairs) {
            int row = warp;
            long d = rowb + s + l + row;
            float4 y = *(const float4*)(Ys + row * 132 + lane * 4);
            float sum = y.x + y.y + y.z + y.w;
            float sq  = y.x * y.x + y.y * y.y + y.z * y.z + y.w * y.w;
            #pragma unroll
            for (int o = 16; o > 0; o >>= 1) {
                sum += __shfl_xor_sync(0xFFFFFFFFu, sum, o);
                sq  += __shfl_xor_sync(0xFFFFFFFFu, sq, o);
            }
            float mu  = sum * (1.f / 128.f);
            float var = sq * (1.f / 128.f) - mu * mu;
            float rs  = rsqrtf(var + 1e-5f);
            float4 wv = ((const float4*)lnw)[lane];
            float4 bv = ((const float4*)lnb)[lane];
            float4 o;
            o.x = (y.x - mu) * rs * wv.x + bv.x;
            o.y = (y.y - mu) * rs * wv.y + bv.y;
            o.z = (y.z - mu) * rs * wv.z + bv.z;
            o.w = (y.w - mu) * rs * wv.w + bv.w;
            unsigned short h0, l0_, h1, l1_, h2, l2_, h3, l3_;
            split2(o.x, h0, l0_); split2(o.y, h1, l1_);
            split2(o.z, h2, l2_); split2(o.w, h3, l3_);
            ((uint2*)g_bufh)[d * 32 + lane] = make_uint2(pk(h0, h1), pk(h2, h3));
            ((uint2*)g_bufl)[d * 32 + lane] = make_uint2(pk(l0_, l1_), pk(l2_, l3_));
        }
        s += 2 * pairs;
        l = (l + 1) >> 1;
        __syncthreads();
    }

    // ---- Gather fused ----
    if (tid < DIM) {
        long idx = ((long)rowb + (2 * L - 2)) * DIM + tid;
        out[item * DIM + tid] =
            __bfloat162float(g_bufh[idx]) + __bfloat162float(g_bufl[idx]);
    }
}

// ---------------------------------------------------------------------------
extern "C" void kernel_launch(void* const* d_in, const int* in_sizes, int n_in,
                              void* d_out, int out_size) {
    const float* args = (const float*)d_in[0];
    const int*   lim  = (const int*)d_in[1];
    const float* W1   = (const float*)d_in[2];
    const float* b1   = (const float*)d_in[3];
    const float* W2   = (const float*)d_in[4];
    const float* b2   = (const float*)d_in[5];
    const float* lnw  = (const float*)d_in[6];
    const float* lnb  = (const float*)d_in[7];
    float* out = (float*)d_out;
    (void)n_in; (void)out_size;

    int T = in_sizes[0] / DIM;

    cudaFuncSetAttribute(k_level_mma, cudaFuncAttributeMaxDynamicSharedMemorySize, 2 * XBYTES);

    dim3 gsc(4, NITEMS);
    k_scatter<<<gsc, 256>>>(args, lim);
    k_scan<<<1, NITEMS>>>(lim);
    k_fillw<<<NITEMS, 256>>>(lim, W1, W2);

    for (int k = 0; k < 4; k++) {
        int mp = (T >> (k + 1)) + NITEMS;
        int cap = NITEMS * (MAXM >> (k + 1));
        if (mp > cap) mp = cap;
        int ctas = (mp + TM - 1) / TM;
        k_level_mma<<<ctas, 256, 2 * XBYTES>>>(b1, b2, lnw, lnb, k);
    }
    k_finish<<<NITEMS, 256>>>(b1, b2, lnw, lnb, lim, out);
}

// round 14
// speedup vs baseline: 1.1479x; 1.1479x over previous
#include <cuda_runtime.h>
#include <cuda_bf16.h>
#include <stdint.h>

#define NITEMS 512
#define MAXM   256
#define DIM    128
#define RPI    512
#define MAXPAIRS 131072
#define TM     32
#define PITCHB 528           // smem row pitch in bytes (264 bf16)
#define XBYTES 16896         // 32 * 528

__device__ __nv_bfloat16  g_bufh [(long)NITEMS * RPI * DIM];
__device__ __nv_bfloat16  g_bufl [(long)NITEMS * RPI * DIM];
// Weight images pre-packed in mma.m16n8k16 B-fragment order:
// [kstep][ntile][lane] -> uint2 (reg b0, reg b1)
__device__ uint2 g_W1hi[16 * 32 * 32];
__device__ uint2 g_W1lo[16 * 32 * 32];
__device__ uint2 g_W2hi[16 * 16 * 32];
__device__ uint2 g_W2lo[16 * 16 * 32];
__device__ int g_src[MAXPAIRS];
__device__ int g_dst[MAXPAIRS];
__device__ int g_off[4 * NITEMS];
__device__ int g_count[4];
__device__ int g_base[4];

__device__ __forceinline__ int get_limit(const int* lim, bool is64, int i) {
    return is64 ? lim[2 * i] : lim[i];
}
__device__ __forceinline__ void split2(float v, unsigned short& h, unsigned short& l) {
    __nv_bfloat16 hb = __float2bfloat16(v);
    __nv_bfloat16 lb = __float2bfloat16(v - __bfloat162float(hb));
    h = __bfloat16_as_ushort(hb); l = __bfloat16_as_ushort(lb);
}
__device__ __forceinline__ uint32_t pk(unsigned short a, unsigned short b) {
    return (uint32_t)a | ((uint32_t)b << 16);
}
__device__ __forceinline__ uint32_t smem_u32(const void* p) {
    uint32_t a;
    asm("{ .reg .u64 t; cvta.to.shared.u64 t, %1; cvt.u32.u64 %0, t; }" : "=r"(a) : "l"(p));
    return a;
}
__device__ __forceinline__ void ldm4(uint32_t* a, uint32_t addr) {
    asm volatile("ldmatrix.sync.aligned.m8n8.x4.shared.b16 {%0,%1,%2,%3}, [%4];"
                 : "=r"(a[0]), "=r"(a[1]), "=r"(a[2]), "=r"(a[3]) : "r"(addr));
}
__device__ __forceinline__ void mma16816(float* c, const uint32_t* a, uint2 b) {
    asm volatile(
        "mma.sync.aligned.m16n8k16.row.col.f32.bf16.bf16.f32 "
        "{%0,%1,%2,%3}, {%4,%5,%6,%7}, {%8,%9}, {%0,%1,%2,%3};"
        : "+f"(c[0]), "+f"(c[1]), "+f"(c[2]), "+f"(c[3])
        : "r"(a[0]), "r"(a[1]), "r"(a[2]), "r"(a[3]), "r"(b.x), "r"(b.y));
}

// ---------------------------------------------------------------------------
__global__ void k_scatter(const float* __restrict__ args, const int* __restrict__ lim) {
    int item = blockIdx.y;
    bool is64 = (lim[1] == 0);
    int start = get_limit(lim, is64, item);
    int L     = get_limit(lim, is64, item + 1) - start;
    int r0 = blockIdx.x * 64;
    int nrows = min(64, L - r0);
    if (nrows <= 0) return;
    const float4* src = (const float4*)(args + (long)(start + r0) * DIM);
    uint2* dh = (uint2*)(g_bufh + ((long)item * RPI + r0) * DIM);
    uint2* dl = (uint2*)(g_bufl + ((long)item * RPI + r0) * DIM);
    int total = nrows * (DIM / 4);
    for (int i = threadIdx.x; i < total; i += blockDim.x) {
        float4 x = src[i];
        unsigned short h0, l0, h1, l1, h2, l2, h3, l3;
        split2(x.x, h0, l0); split2(x.y, h1, l1);
        split2(x.z, h2, l2); split2(x.w, h3, l3);
        dh[i] = make_uint2(pk(h0, h1), pk(h2, h3));
        dl[i] = make_uint2(pk(l0, l1), pk(l2, l3));
    }
}

// ---------------------------------------------------------------------------
__global__ void k_scan(const int* __restrict__ lim) {
    __shared__ int sc[NITEMS];
    int i = threadIdx.x;
    bool is64 = (lim[1] == 0);
    int L = get_limit(lim, is64, i + 1) - get_limit(lim, is64, i);
    int l = L, base = 0;
    for (int k = 0; k < 4; k++) {
        int pr = l >> 1;
        sc[i] = pr;
        __syncthreads();
        for (int off = 1; off < NITEMS; off <<= 1) {
            int v = sc[i];
            int w = (i >= off) ? sc[i - off] : 0;
            __syncthreads();
            sc[i] = v + w;
            __syncthreads();
        }
        g_off[k * NITEMS + i] = sc[i] - pr;
        if (i == 0) { g_count[k] = sc[NITEMS - 1]; g_base[k] = base; }
        base += sc[NITEMS - 1];
        l = (l + 1) >> 1;
        __syncthreads();
    }
}

// ---------------------------------------------------------------------------
__global__ void k_fillw(const int* __restrict__ lim,
                        const float* __restrict__ W1, const float* __restrict__ W2) {
    if (blockIdx.x < 64) {
        int g = blockIdx.x * 256 + threadIdx.x;        // [0, 16384)
        int kstep = g >> 10, ntile = (g >> 5) & 31, lane = g & 31;
        int kb = kstep * 16 + (lane & 3) * 2;
        {
            int n = ntile * 8 + (lane >> 2);
            unsigned short h00, l00, h01, l01, h10, l10, h11, l11;
            split2(W1[kb * 256 + n],       h00, l00);
            split2(W1[(kb + 1) * 256 + n], h01, l01);
            split2(W1[(kb + 8) * 256 + n], h10, l10);
            split2(W1[(kb + 9) * 256 + n], h11, l11);
            int idx = (kstep * 32 + ntile) * 32 + lane;
            g_W1hi[idx] = make_uint2(pk(h00, h01), pk(h10, h11));
            g_W1lo[idx] = make_uint2(pk(l00, l01), pk(l10, l11));
        }
        if (ntile < 16) {
            int n = ntile * 8 + (lane >> 2);
            unsigned short h00, l00, h01, l01, h10, l10, h11, l11;
            split2(W2[kb * 128 + n],       h00, l00);
            split2(W2[(kb + 1) * 128 + n], h01, l01);
            split2(W2[(kb + 8) * 128 + n], h10, l10);
            split2(W2[(kb + 9) * 128 + n], h11, l11);
            int idx = (kstep * 16 + ntile) * 32 + lane;
            g_W2hi[idx] = make_uint2(pk(h00, h01), pk(h10, h11));
            g_W2lo[idx] = make_uint2(pk(l00, l01), pk(l10, l11));
        }
    }
    int item = blockIdx.x;
    bool is64 = (lim[1] == 0);
    int L = get_limit(lim, is64, item + 1) - get_limit(lim, is64, item);
    int s = 0, l = L;
    int rowb = item * RPI;
    for (int k = 0; k < 4; k++) {
        int pr = l >> 1;
        int e = g_base[k] + g_off[k * NITEMS + item];
        for (int p = threadIdx.x; p < pr; p += blockDim.x) {
            g_src[e + p] = rowb + s + 2 * p;
            g_dst[e + p] = rowb + s + l + p;
        }
        s += 2 * pr;
        l = (l + 1) >> 1;
    }
}

// ---------------------------------------------------------------------------
// Batched level kernel (levels 0..3): 32 pairs/CTA, 8 warps (1 M x 8 N).
// acc = 32 regs/thread -> ~80 regs total -> 3 CTAs/SM (6 warps/SMSP).
// All warps share the same A rows (ldmatrix broadcast); no B duplication.
// ---------------------------------------------------------------------------
extern __shared__ __align__(16) unsigned char smraw[];

__global__ void __launch_bounds__(256, 3) k_level_mma(
    const float* __restrict__ b1, const float* __restrict__ b2,
    const float* __restrict__ lnw, const float* __restrict__ lnb, int level)
{
    int cnt = g_count[level], base = g_base[level];
    int j0 = blockIdx.x * TM;
    if (j0 >= cnt) return;
    int np = min(TM, cnt - j0);

    unsigned char* Xhi = smraw;
    unsigned char* Xlo = smraw + XBYTES;
    uint32_t XhiA = smem_u32(Xhi);
    uint32_t XloA = XhiA + XBYTES;

    int tid = threadIdx.x;
    int warp = tid >> 5, lane = tid & 31;

    // ---- Gather X: 32 pairs x 32 uint4 ----
    {
        const uint4* sh = (const uint4*)g_bufh;
        const uint4* sl = (const uint4*)g_bufl;
        #pragma unroll
        for (int it = 0; it < 4; it++) {
            int f = it * 256 + tid;
            int r = f >> 5, q = f & 31;
            int rc = min(r, np - 1);
            int sr = g_src[base + j0 + rc];
            *(uint4*)(Xhi + r * PITCHB + q * 16) = sh[(long)sr * 16 + q];
            *(uint4*)(Xlo + r * PITCHB + q * 16) = sl[(long)sr * 16 + q];
        }
    }
    __syncthreads();

    int lrow = lane & 15;
    int lcol = (lane >> 4) << 3;
    uint32_t rowA0 = (uint32_t)lrow * PITCHB;
    uint32_t rowA1 = (uint32_t)(16 + lrow) * PITCHB;

    // ---- GEMM1: warp tile 32 x 32 (4 ntiles), fused 3-term ----
    float acc[2][4][4];
    #pragma unroll
    for (int rb = 0; rb < 2; rb++)
        #pragma unroll
        for (int nt = 0; nt < 4; nt++)
            #pragma unroll
            for (int e = 0; e < 4; e++) acc[rb][nt][e] = 0.f;

    #pragma unroll 2
    for (int ks = 0; ks < 16; ks++) {
        uint32_t col2 = (uint32_t)(ks * 16 + lcol) * 2;
        uint32_t ah0[4], ah1[4], al0[4], al1[4];
        ldm4(ah0, XhiA + rowA0 + col2);
        ldm4(ah1, XhiA + rowA1 + col2);
        ldm4(al0, XloA + rowA0 + col2);
        ldm4(al1, XloA + rowA1 + col2);
        #pragma unroll
        for (int nt = 0; nt < 4; nt++) {
            int bi = (ks * 32 + warp * 4 + nt) * 32 + lane;
            uint2 bh = g_W1hi[bi];
            uint2 bl = g_W1lo[bi];
            mma16816(acc[0][nt], ah0, bh);
            mma16816(acc[1][nt], ah1, bh);
            mma16816(acc[0][nt], ah0, bl);
            mma16816(acc[1][nt], ah1, bl);
            mma16816(acc[0][nt], al0, bh);
            mma16816(acc[1][nt], al1, bh);
        }
    }
    __syncthreads();

    // ---- Epilogue1: H = relu(acc + b1) -> X images ----
    #pragma unroll
    for (int rb = 0; rb < 2; rb++) {
        int row = rb * 16 + (lane >> 2);
        #pragma unroll
        for (int nt = 0; nt < 4; nt++) {
            int col = (warp * 4 + nt) * 8 + (lane & 3) * 2;
            float v0 = fmaxf(acc[rb][nt][0] + b1[col], 0.f);
            float v1 = fmaxf(acc[rb][nt][1] + b1[col + 1], 0.f);
            float v2 = fmaxf(acc[rb][nt][2] + b1[col], 0.f);
            float v3 = fmaxf(acc[rb][nt][3] + b1[col + 1], 0.f);
            unsigned short h0, l0, h1, l1, h2, l2, h3, l3;
            split2(v0, h0, l0); split2(v1, h1, l1);
            split2(v2, h2, l2); split2(v3, h3, l3);
            *(uint32_t*)(Xhi + row * PITCHB + col * 2)       = pk(h0, h1);
            *(uint32_t*)(Xlo + row * PITCHB + col * 2)       = pk(l0, l1);
            *(uint32_t*)(Xhi + (row + 8) * PITCHB + col * 2) = pk(h2, h3);
            *(uint32_t*)(Xlo + (row + 8) * PITCHB + col * 2) = pk(l2, l3);
        }
    }
    __syncthreads();

    // ---- GEMM2: warp tile 32 x 16 (2 ntiles), fused 3-term ----
    float acc2[2][2][4];
    #pragma unroll
    for (int rb = 0; rb < 2; rb++)
        #pragma unroll
        for (int nt = 0; nt < 2; nt++)
            #pragma unroll
            for (int e = 0; e < 4; e++) acc2[rb][nt][e] = 0.f;

    #pragma unroll 2
    for (int ks = 0; ks < 16; ks++) {
        uint32_t col2 = (uint32_t)(ks * 16 + lcol) * 2;
        uint32_t ah0[4], ah1[4], al0[4], al1[4];
        ldm4(ah0, XhiA + rowA0 + col2);
        ldm4(ah1, XhiA + rowA1 + col2);
        ldm4(al0, XloA + rowA0 + col2);
        ldm4(al1, XloA + rowA1 + col2);
        #pragma unroll
        for (int nt = 0; nt < 2; nt++) {
            int bi = (ks * 16 + warp * 2 + nt) * 32 + lane;
            uint2 bh = g_W2hi[bi];
            uint2 bl = g_W2lo[bi];
            mma16816(acc2[0][nt], ah0, bh);
            mma16816(acc2[1][nt], ah1, bh);
            mma16816(acc2[0][nt], ah0, bl);
            mma16816(acc2[1][nt], ah1, bl);
            mma16816(acc2[0][nt], al0, bh);
            mma16816(acc2[1][nt], al1, bh);
        }
    }
    __syncthreads();

    // ---- Epilogue2a: Y -> f32 smem [32][132] (fits Xhi exactly) ----
    float* Ys = (float*)Xhi;
    #pragma unroll
    for (int rb = 0; rb < 2; rb++) {
        int row = rb * 16 + (lane >> 2);
        #pragma unroll
        for (int nt = 0; nt < 2; nt++) {
            int col = (warp * 2 + nt) * 8 + (lane & 3) * 2;
            *(float2*)(Ys + row * 132 + col) =
                make_float2(acc2[rb][nt][0] + b2[col], acc2[rb][nt][1] + b2[col + 1]);
            *(float2*)(Ys + (row + 8) * 132 + col) =
                make_float2(acc2[rb][nt][2] + b2[col], acc2[rb][nt][3] + b2[col + 1]);
        }
    }
    __syncthreads();

    // ---- Epilogue2b: LayerNorm + store hi/lo (4 rows per warp) ----
    #pragma unroll
    for (int rr = 0; rr < 4; rr++) {
        int row = warp * 4 + rr;
        int d = (row < np) ? g_dst[base + j0 + row] : -1;
        float4 y = *(const float4*)(Ys + row * 132 + lane * 4);
        float sum = y.x + y.y + y.z + y.w;
        float sq  = y.x * y.x + y.y * y.y + y.z * y.z + y.w * y.w;
        #pragma unroll
        for (int o = 16; o > 0; o >>= 1) {
            sum += __shfl_xor_sync(0xFFFFFFFFu, sum, o);
            sq  += __shfl_xor_sync(0xFFFFFFFFu, sq, o);
        }
        float mu  = sum * (1.f / 128.f);
        float var = sq * (1.f / 128.f) - mu * mu;
        float rs  = rsqrtf(var + 1e-5f);
        float4 wv = ((const float4*)lnw)[lane];
        float4 bv = ((const float4*)lnb)[lane];
        float4 o;
        o.x = (y.x - mu) * rs * wv.x + bv.x;
        o.y = (y.y - mu) * rs * wv.y + bv.y;
        o.z = (y.z - mu) * rs * wv.z + bv.z;
        o.w = (y.w - mu) * rs * wv.w + bv.w;
        if (d >= 0) {
            unsigned short h0, l0, h1, l1, h2, l2, h3, l3;
            split2(o.x, h0, l0); split2(o.y, h1, l1);
            split2(o.z, h2, l2); split2(o.w, h3, l3);
            ((uint2*)g_bufh)[(long)d * 32 + lane] = make_uint2(pk(h0, h1), pk(h2, h3));
            ((uint2*)g_bufl)[(long)d * 32 + lane] = make_uint2(pk(l0, l1), pk(l2, l3));
        }
    }
}

// ---------------------------------------------------------------------------
// Finisher: one CTA per item, levels 4..7 + fused gather.
// ---------------------------------------------------------------------------
__global__ void __launch_bounds__(256, 4) k_finish(
    const float* __restrict__ b1, const float* __restrict__ b2,
    const float* __restrict__ lnw, const float* __restrict__ lnb,
    const int* __restrict__ lim, float* __restrict__ out)
{
    __shared__ __align__(16) unsigned char Xhi[16 * PITCHB];   // 8448 B
    __shared__ __align__(16) unsigned char Xlo[16 * PITCHB];

    int item = blockIdx.x;
    bool is64 = (lim[1] == 0);
    int L = get_limit(lim, is64, item + 1) - get_limit(lim, is64, item);
    int s = 0, l = L;
    #pragma unroll
    for (int t = 0; t < 4; t++) { int pr = l >> 1; s += 2 * pr; l = (l + 1) >> 1; }
    int rowb = item * RPI;

    uint32_t XhiA = smem_u32(Xhi);
    uint32_t XloA = smem_u32(Xlo);
    int tid = threadIdx.x;
    int warp = tid >> 5, lane = tid & 31;
    int lrow = lane & 15;
    int lcol = (lane >> 4) << 3;
    uint32_t rowA = (uint32_t)lrow * PITCHB;

    #pragma unroll 1
    for (int lev = 0; lev < 4 && l >= 2; lev++) {
        int pairs = l >> 1;    // 1..8

        {
            const uint4* sh = (const uint4*)g_bufh;
            const uint4* sl = (const uint4*)g_bufl;
            int tot = pairs * 32;
            for (int f = tid; f < tot; f += 256) {
                int r = f >> 5, q = f & 31;
                long gsrc = (long)(rowb + s + 2 * r) * 16 + q;
                *(uint4*)(Xhi + r * PITCHB + q * 16) = sh[gsrc];
                *(uint4*)(Xlo + r * PITCHB + q * 16) = sl[gsrc];
            }
        }
        __syncthreads();

        // GEMM1: warp tile 16 x 32
        float acc[4][4];
        #pragma unroll
        for (int nt = 0; nt < 4; nt++)
            #pragma unroll
            for (int e = 0; e < 4; e++) acc[nt][e] = 0.f;
        #pragma unroll 2
        for (int ks = 0; ks < 16; ks++) {
            uint32_t col2 = (uint32_t)(ks * 16 + lcol) * 2;
            uint32_t ah[4], al[4];
            ldm4(ah, XhiA + rowA + col2);
            ldm4(al, XloA + rowA + col2);
            #pragma unroll
            for (int nt = 0; nt < 4; nt++) {
                int bi = (ks * 32 + warp * 4 + nt) * 32 + lane;
                uint2 bh = g_W1hi[bi];
                uint2 bl = g_W1lo[bi];
                mma16816(acc[nt], ah, bh);
                mma16816(acc[nt], ah, bl);
                mma16816(acc[nt], al, bh);
            }
        }
        __syncthreads();

        {
            int row = lane >> 2;
            #pragma unroll
            for (int nt = 0; nt < 4; nt++) {
                int col = (warp * 4 + nt) * 8 + (lane & 3) * 2;
                float v0 = fmaxf(acc[nt][0] + b1[col], 0.f);
                float v1 = fmaxf(acc[nt][1] + b1[col + 1], 0.f);
                float v2 = fmaxf(acc[nt][2] + b1[col], 0.f);
                float v3 = fmaxf(acc[nt][3] + b1[col + 1], 0.f);
                unsigned short h0, l0_, h1, l1_, h2, l2_, h3, l3_;
                split2(v0, h0, l0_); split2(v1, h1, l1_);
                split2(v2, h2, l2_); split2(v3, h3, l3_);
                *(uint32_t*)(Xhi + row * PITCHB + col * 2)       = pk(h0, h1);
                *(uint32_t*)(Xlo + row * PITCHB + col * 2)       = pk(l0_, l1_);
                *(uint32_t*)(Xhi + (row + 8) * PITCHB + col * 2) = pk(h2, h3);
                *(uint32_t*)(Xlo + (row + 8) * PITCHB + col * 2) = pk(l2_, l3_);
            }
        }
        __syncthreads();

        // GEMM2: warp tile 16 x 16
        float acc2[2][4];
        #pragma unroll
        for (int nt = 0; nt < 2; nt++)
            #pragma unroll
            for (int e = 0; e < 4; e++) acc2[nt][e] = 0.f;
        #pragma unroll 2
        for (int ks = 0; ks < 16; ks++) {
            uint32_t col2 = (uint32_t)(ks * 16 + lcol) * 2;
            uint32_t ah[4], al[4];
            ldm4(ah, XhiA + rowA + col2);
            ldm4(al, XloA + rowA + col2);
            #pragma unroll
            for (int nt = 0; nt < 2; nt++) {
                int bi = (ks * 16 + warp * 2 + nt) * 32 + lane;
                uint2 bh = g_W2hi[bi];
                uint2 bl = g_W2lo[bi];
                mma16816(acc2[nt], ah, bh);
                mma16816(acc2[nt], ah, bl);
                mma16816(acc2[nt], al, bh);
            }
        }
        __syncthreads();

        float* Ys = (float*)Xhi;
        {
            int row = lane >> 2;
            #pragma unroll
            for (int nt = 0; nt < 2; nt++) {
                int col = (warp * 2 + nt) * 8 + (lane & 3) * 2;
                *(float2*)(Ys + row * 132 + col) =
                    make_float2(acc2[nt][0] + b2[col], acc2[nt][1] + b2[col + 1]);
                *(float2*)(Ys + (row + 8) * 132 + col) =
                    make_float2(acc2[nt][2] + b2[col], acc2[nt][3] + b2[col + 1]);
            }
        }
        __syncthreads();

        if (warp < pairs) {
            int row = warp;
            long d = rowb + s + l + row;
            float4 y = *(const float4*)(Ys + row * 132 + lane * 4);
            float sum = y.x + y.y + y.z + y.w;
            float sq  = y.x * y.x + y.y * y.y + y.z * y.z + y.w * y.w;
            #pragma unroll
            for (int o = 16; o > 0; o >>= 1) {
                sum += __shfl_xor_sync(0xFFFFFFFFu, sum, o);
                sq  += __shfl_xor_sync(0xFFFFFFFFu, sq, o);
            }
            float mu  = sum * (1.f / 128.f);
            float var = sq * (1.f / 128.f) - mu * mu;
            float rs  = rsqrtf(var + 1e-5f);
            float4 wv = ((const float4*)lnw)[lane];
            float4 bv = ((const float4*)lnb)[lane];
            float4 o;
            o.x = (y.x - mu) * rs * wv.x + bv.x;
            o.y = (y.y - mu) * rs * wv.y + bv.y;
            o.z = (y.z - mu) * rs * wv.z + bv.z;
            o.w = (y.w - mu) * rs * wv.w + bv.w;
            unsigned short h0, l0_, h1, l1_, h2, l2_, h3, l3_;
            split2(o.x, h0, l0_); split2(o.y, h1, l1_);
            split2(o.z, h2, l2_); split2(o.w, h3, l3_);
            ((uint2*)g_bufh)[d * 32 + lane] = make_uint2(pk(h0, h1), pk(h2, h3));
            ((uint2*)g_bufl)[d * 32 + lane] = make_uint2(pk(l0_, l1_), pk(l2_, l3_));
        }
        s += 2 * pairs;
        l = (l + 1) >> 1;
        __syncthreads();
    }

    // ---- Gather fused ----
    if (tid < DIM) {
        long idx = ((long)rowb + (2 * L - 2)) * DIM + tid;
        out[item * DIM + tid] =
            __bfloat162float(g_bufh[idx]) + __bfloat162float(g_bufl[idx]);
    }
}

// ---------------------------------------------------------------------------
extern "C" void kernel_launch(void* const* d_in, const int* in_sizes, int n_in,
                              void* d_out, int out_size) {
    const float* args = (const float*)d_in[0];
    const int*   lim  = (const int*)d_in[1];
    const float* W1   = (const float*)d_in[2];
    const float* b1   = (const float*)d_in[3];
    const float* W2   = (const float*)d_in[4];
    const float* b2   = (const float*)d_in[5];
    const float* lnw  = (const float*)d_in[6];
    const float* lnb  = (const float*)d_in[7];
    float* out = (float*)d_out;
    (void)n_in; (void)out_size;

    int T = in_sizes[0] / DIM;

    cudaFuncSetAttribute(k_level_mma, cudaFuncAttributeMaxDynamicSharedMemorySize, 2 * XBYTES);

    dim3 gsc(4, NITEMS);
    k_scatter<<<gsc, 256>>>(args, lim);
    k_scan<<<1, NITEMS>>>(lim);
    k_fillw<<<NITEMS, 256>>>(lim, W1, W2);

    for (int k = 0; k < 4; k++) {
        int mp = (T >> (k + 1)) + NITEMS;
        int cap = NITEMS * (MAXM >> (k + 1));
        if (mp > cap) mp = cap;
        int ctas = (mp + TM - 1) / TM;
        k_level_mma<<<ctas, 256, 2 * XBYTES>>>(b1, b2, lnw, lnb, k);
    }
    k_finish<<<NITEMS, 256>>>(b1, b2, lnw, lnb, lim, out);
}

// round 15
// speedup vs baseline: 1.3193x; 1.1493x over previous
#include <cuda_runtime.h>
#include <cuda_bf16.h>
#include <stdint.h>

#define NITEMS 512
#define MAXM   256
#define DIM    128
#define RPI    512
#define MAXPAIRS 131072
#define TM     32
#define PITCHB 528           // smem row pitch in bytes (264 bf16)
#define XBYTES 16896         // 32 * 528

__device__ __nv_bfloat16  g_bufh [(long)NITEMS * RPI * DIM];
__device__ __nv_bfloat16  g_bufl [(long)NITEMS * RPI * DIM];
// Interleaved weight images in mma B-fragment order:
// [kstep][ntile][lane] -> uint4 { bh.x, bh.y, bl.x, bl.y }
__device__ uint4 g_W1p[16 * 32 * 32];   // 256 KB
__device__ uint4 g_W2p[16 * 16 * 32];   // 128 KB
__device__ int g_src[MAXPAIRS];
__device__ int g_dst[MAXPAIRS];
__device__ int g_off[4 * NITEMS];
__device__ int g_count[4];
__device__ int g_base[4];

__device__ __forceinline__ int get_limit(const int* lim, bool is64, int i) {
    return is64 ? lim[2 * i] : lim[i];
}
__device__ __forceinline__ void split2(float v, unsigned short& h, unsigned short& l) {
    __nv_bfloat16 hb = __float2bfloat16(v);
    __nv_bfloat16 lb = __float2bfloat16(v - __bfloat162float(hb));
    h = __bfloat16_as_ushort(hb); l = __bfloat16_as_ushort(lb);
}
__device__ __forceinline__ uint32_t pk(unsigned short a, unsigned short b) {
    return (uint32_t)a | ((uint32_t)b << 16);
}
__device__ __forceinline__ uint32_t smem_u32(const void* p) {
    uint32_t a;
    asm("{ .reg .u64 t; cvta.to.shared.u64 t, %1; cvt.u32.u64 %0, t; }" : "=r"(a) : "l"(p));
    return a;
}
__device__ __forceinline__ void ldm4(uint32_t* a, uint32_t addr) {
    asm volatile("ldmatrix.sync.aligned.m8n8.x4.shared.b16 {%0,%1,%2,%3}, [%4];"
                 : "=r"(a[0]), "=r"(a[1]), "=r"(a[2]), "=r"(a[3]) : "r"(addr));
}
__device__ __forceinline__ void mma16816(float* c, const uint32_t* a, uint32_t b0, uint32_t b1) {
    asm volatile(
        "mma.sync.aligned.m16n8k16.row.col.f32.bf16.bf16.f32 "
        "{%0,%1,%2,%3}, {%4,%5,%6,%7}, {%8,%9}, {%0,%1,%2,%3};"
        : "+f"(c[0]), "+f"(c[1]), "+f"(c[2]), "+f"(c[3])
        : "r"(a[0]), "r"(a[1]), "r"(a[2]), "r"(a[3]), "r"(b0), "r"(b1));
}

// ---------------------------------------------------------------------------
// Scan: warp-shuffle two-stage inclusive scan, levels 0..3.
// ---------------------------------------------------------------------------
__global__ void k_scan(const int* __restrict__ lim) {
    __shared__ int wsum[16];
    int i = threadIdx.x, lane = i & 31, w = i >> 5;
    bool is64 = (lim[1] == 0);
    int L = get_limit(lim, is64, i + 1) - get_limit(lim, is64, i);
    int l = L, base = 0;
    for (int k = 0; k < 4; k++) {
        int pr = l >> 1;
        int v = pr;
        #pragma unroll
        for (int o = 1; o < 32; o <<= 1) {
            int t = __shfl_up_sync(0xFFFFFFFFu, v, o);
            if (lane >= o) v += t;
        }
        if (lane == 31) wsum[w] = v;
        __syncthreads();
        if (w == 0 && lane < 16) {
            int s = wsum[lane];
            #pragma unroll
            for (int o = 1; o < 16; o <<= 1) {
                int t = __shfl_up_sync(0x0000FFFFu, s, o);
                if (lane >= o) s += t;
            }
            wsum[lane] = s;
        }
        __syncthreads();
        int incl = v + ((w > 0) ? wsum[w - 1] : 0);
        g_off[k * NITEMS + i] = incl - pr;
        if (i == 0) { g_count[k] = wsum[15]; g_base[k] = base; }
        base += wsum[15];
        l = (l + 1) >> 1;
        __syncthreads();
    }
}

// ---------------------------------------------------------------------------
// Fill pair lists (levels 0..3; level-0 src = ARGS row), weight packing
// (blocks 0..63), and odd-carry leaf splits (the only leaves read post-L0).
// ---------------------------------------------------------------------------
__global__ void k_fillw(const int* __restrict__ lim, const float* __restrict__ args,
                        const float* __restrict__ W1, const float* __restrict__ W2) {
    if (blockIdx.x < 64) {
        int g = blockIdx.x * 256 + threadIdx.x;        // [0, 16384)
        int kstep = g >> 10, ntile = (g >> 5) & 31, lane = g & 31;
        int kb = kstep * 16 + (lane & 3) * 2;
        {
            int n = ntile * 8 + (lane >> 2);
            unsigned short h00, l00, h01, l01, h10, l10, h11, l11;
            split2(W1[kb * 256 + n],       h00, l00);
            split2(W1[(kb + 1) * 256 + n], h01, l01);
            split2(W1[(kb + 8) * 256 + n], h10, l10);
            split2(W1[(kb + 9) * 256 + n], h11, l11);
            g_W1p[(kstep * 32 + ntile) * 32 + lane] =
                make_uint4(pk(h00, h01), pk(h10, h11), pk(l00, l01), pk(l10, l11));
        }
        if (ntile < 16) {
            int n = ntile * 8 + (lane >> 2);
            unsigned short h00, l00, h01, l01, h10, l10, h11, l11;
            split2(W2[kb * 128 + n],       h00, l00);
            split2(W2[(kb + 1) * 128 + n], h01, l01);
            split2(W2[(kb + 8) * 128 + n], h10, l10);
            split2(W2[(kb + 9) * 128 + n], h11, l11);
            g_W2p[(kstep * 16 + ntile) * 32 + lane] =
                make_uint4(pk(h00, h01), pk(h10, h11), pk(l00, l01), pk(l10, l11));
        }
    }
    int item = blockIdx.x;
    bool is64 = (lim[1] == 0);
    int start = get_limit(lim, is64, item);
    int L = get_limit(lim, is64, item + 1) - start;
    int rowb = item * RPI;

    // Odd-carry leaf: row L-1 survives level 0 (also the L==1 root for gather)
    if ((L & 1) && threadIdx.x < DIM) {
        float x = args[(long)(start + L - 1) * DIM + threadIdx.x];
        unsigned short h, l; split2(x, h, l);
        long d = (long)(rowb + L - 1) * DIM + threadIdx.x;
        g_bufh[d] = __ushort_as_bfloat16(h);
        g_bufl[d] = __ushort_as_bfloat16(l);
    }

    int s = 0, l = L;
    for (int k = 0; k < 4; k++) {
        int pr = l >> 1;
        int e = g_base[k] + g_off[k * NITEMS + item];
        for (int p = threadIdx.x; p < pr; p += blockDim.x) {
            g_src[e + p] = (k == 0) ? (start + 2 * p) : (rowb + s + 2 * p);
            g_dst[e + p] = rowb + s + l + p;
        }
        s += 2 * pr;
        l = (l + 1) >> 1;
    }
}

// ---------------------------------------------------------------------------
// Batched level kernel (levels 0..3): 32 pairs/CTA, 8 warps (1 M x 8 N).
// Level 0 gathers from args (fp32, split in-kernel); levels >=1 from g_buf.
// ---------------------------------------------------------------------------
extern __shared__ __align__(16) unsigned char smraw[];

__global__ void __launch_bounds__(256, 3) k_level_mma(
    const float* __restrict__ args,
    const float* __restrict__ b1, const float* __restrict__ b2,
    const float* __restrict__ lnw, const float* __restrict__ lnb, int level)
{
    int cnt = g_count[level], base = g_base[level];
    int j0 = blockIdx.x * TM;
    if (j0 >= cnt) return;
    int np = min(TM, cnt - j0);

    unsigned char* Xhi = smraw;
    unsigned char* Xlo = smraw + XBYTES;
    uint32_t XhiA = smem_u32(Xhi);
    uint32_t XloA = XhiA + XBYTES;

    int tid = threadIdx.x;
    int warp = tid >> 5, lane = tid & 31;

    // ---- Gather X ----
    if (level == 0) {
        // pair = 2 contiguous args rows = 256 floats = 64 float4; split here
        const float4* af = (const float4*)args;
        #pragma unroll
        for (int it = 0; it < 8; it++) {
            int f = it * 256 + tid;            // [0, 2048)
            int r = f >> 6, q = f & 63;
            int rc = min(r, np - 1);
            int sr = g_src[base + j0 + rc];    // args row index
            float4 x = af[(long)sr * 32 + q];
            unsigned short h0, l0, h1, l1, h2, l2, h3, l3;
            split2(x.x, h0, l0); split2(x.y, h1, l1);
            split2(x.z, h2, l2); split2(x.w, h3, l3);
            *(uint2*)(Xhi + r * PITCHB + q * 8) = make_uint2(pk(h0, h1), pk(h2, h3));
            *(uint2*)(Xlo + r * PITCHB + q * 8) = make_uint2(pk(l0, l1), pk(l2, l3));
        }
    } else {
        const uint4* sh = (const uint4*)g_bufh;
        const uint4* sl = (const uint4*)g_bufl;
        #pragma unroll
        for (int it = 0; it < 4; it++) {
            int f = it * 256 + tid;
            int r = f >> 5, q = f & 31;
            int rc = min(r, np - 1);
            int sr = g_src[base + j0 + rc];
            *(uint4*)(Xhi + r * PITCHB + q * 16) = sh[(long)sr * 16 + q];
            *(uint4*)(Xlo + r * PITCHB + q * 16) = sl[(long)sr * 16 + q];
        }
    }
    __syncthreads();

    int lrow = lane & 15;
    int lcol = (lane >> 4) << 3;
    uint32_t rowA0 = (uint32_t)lrow * PITCHB;
    uint32_t rowA1 = (uint32_t)(16 + lrow) * PITCHB;

    // ---- GEMM1: warp tile 32 x 32 (4 ntiles), fused 3-term ----
    float acc[2][4][4];
    #pragma unroll
    for (int rb = 0; rb < 2; rb++)
        #pragma unroll
        for (int nt = 0; nt < 4; nt++)
            #pragma unroll
            for (int e = 0; e < 4; e++) acc[rb][nt][e] = 0.f;

    #pragma unroll 2
    for (int ks = 0; ks < 16; ks++) {
        uint32_t col2 = (uint32_t)(ks * 16 + lcol) * 2;
        uint32_t ah0[4], ah1[4], al0[4], al1[4];
        ldm4(ah0, XhiA + rowA0 + col2);
        ldm4(ah1, XhiA + rowA1 + col2);
        ldm4(al0, XloA + rowA0 + col2);
        ldm4(al1, XloA + rowA1 + col2);
        #pragma unroll
        for (int nt = 0; nt < 4; nt++) {
            uint4 b = g_W1p[(ks * 32 + warp * 4 + nt) * 32 + lane];
            mma16816(acc[0][nt], ah0, b.x, b.y);
            mma16816(acc[1][nt], ah1, b.x, b.y);
            mma16816(acc[0][nt], ah0, b.z, b.w);
            mma16816(acc[1][nt], ah1, b.z, b.w);
            mma16816(acc[0][nt], al0, b.x, b.y);
            mma16816(acc[1][nt], al1, b.x, b.y);
        }
    }
    __syncthreads();

    // ---- Epilogue1: H = relu(acc + b1) -> X images ----
    #pragma unroll
    for (int rb = 0; rb < 2; rb++) {
        int row = rb * 16 + (lane >> 2);
        #pragma unroll
        for (int nt = 0; nt < 4; nt++) {
            int col = (warp * 4 + nt) * 8 + (lane & 3) * 2;
            float v0 = fmaxf(acc[rb][nt][0] + b1[col], 0.f);
            float v1 = fmaxf(acc[rb][nt][1] + b1[col + 1], 0.f);
            float v2 = fmaxf(acc[rb][nt][2] + b1[col], 0.f);
            float v3 = fmaxf(acc[rb][nt][3] + b1[col + 1], 0.f);
            unsigned short h0, l0, h1, l1, h2, l2, h3, l3;
            split2(v0, h0, l0); split2(v1, h1, l1);
            split2(v2, h2, l2); split2(v3, h3, l3);
            *(uint32_t*)(Xhi + row * PITCHB + col * 2)       = pk(h0, h1);
            *(uint32_t*)(Xlo + row * PITCHB + col * 2)       = pk(l0, l1);
            *(uint32_t*)(Xhi + (row + 8) * PITCHB + col * 2) = pk(h2, h3);
            *(uint32_t*)(Xlo + (row + 8) * PITCHB + col * 2) = pk(l2, l3);
        }
    }
    __syncthreads();

    // ---- GEMM2: warp tile 32 x 16 (2 ntiles), fused 3-term ----
    float acc2[2][2][4];
    #pragma unroll
    for (int rb = 0; rb < 2; rb++)
        #pragma unroll
        for (int nt = 0; nt < 2; nt++)
            #pragma unroll
            for (int e = 0; e < 4; e++) acc2[rb][nt][e] = 0.f;

    #pragma unroll 2
    for (int ks = 0; ks < 16; ks++) {
        uint32_t col2 = (uint32_t)(ks * 16 + lcol) * 2;
        uint32_t ah0[4], ah1[4], al0[4], al1[4];
        ldm4(ah0, XhiA + rowA0 + col2);
        ldm4(ah1, XhiA + rowA1 + col2);
        ldm4(al0, XloA + rowA0 + col2);
        ldm4(al1, XloA + rowA1 + col2);
        #pragma unroll
        for (int nt = 0; nt < 2; nt++) {
            uint4 b = g_W2p[(ks * 16 + warp * 2 + nt) * 32 + lane];
            mma16816(acc2[0][nt], ah0, b.x, b.y);
            mma16816(acc2[1][nt], ah1, b.x, b.y);
            mma16816(acc2[0][nt], ah0, b.z, b.w);
            mma16816(acc2[1][nt], ah1, b.z, b.w);
            mma16816(acc2[0][nt], al0, b.x, b.y);
            mma16816(acc2[1][nt], al1, b.x, b.y);
        }
    }
    __syncthreads();

    // ---- Epilogue2a: Y -> f32 smem [32][132] ----
    float* Ys = (float*)Xhi;
    #pragma unroll
    for (int rb = 0; rb < 2; rb++) {
        int row = rb * 16 + (lane >> 2);
        #pragma unroll
        for (int nt = 0; nt < 2; nt++) {
            int col = (warp * 2 + nt) * 8 + (lane & 3) * 2;
            *(float2*)(Ys + row * 132 + col) =
                make_float2(acc2[rb][nt][0] + b2[col], acc2[rb][nt][1] + b2[col + 1]);
            *(float2*)(Ys + (row + 8) * 132 + col) =
                make_float2(acc2[rb][nt][2] + b2[col], acc2[rb][nt][3] + b2[col + 1]);
        }
    }
    __syncthreads();

    // ---- Epilogue2b: LayerNorm + store hi/lo ----
    #pragma unroll
    for (int rr = 0; rr < 4; rr++) {
        int row = warp * 4 + rr;
        int d = (row < np) ? g_dst[base + j0 + row] : -1;
        float4 y = *(const float4*)(Ys + row * 132 + lane * 4);
        float sum = y.x + y.y + y.z + y.w;
        float sq  = y.x * y.x + y.y * y.y + y.z * y.z + y.w * y.w;
        #pragma unroll
        for (int o = 16; o > 0; o >>= 1) {
            sum += __shfl_xor_sync(0xFFFFFFFFu, sum, o);
            sq  += __shfl_xor_sync(0xFFFFFFFFu, sq, o);
        }
        float mu  = sum * (1.f / 128.f);
        float var = sq * (1.f / 128.f) - mu * mu;
        float rs  = rsqrtf(var + 1e-5f);
        float4 wv = ((const float4*)lnw)[lane];
        float4 bv = ((const float4*)lnb)[lane];
        float4 o;
        o.x = (y.x - mu) * rs * wv.x + bv.x;
        o.y = (y.y - mu) * rs * wv.y + bv.y;
        o.z = (y.z - mu) * rs * wv.z + bv.z;
        o.w = (y.w - mu) * rs * wv.w + bv.w;
        if (d >= 0) {
            unsigned short h0, l0, h1, l1, h2, l2, h3, l3;
            split2(o.x, h0, l0); split2(o.y, h1, l1);
            split2(o.z, h2, l2); split2(o.w, h3, l3);
            ((uint2*)g_bufh)[(long)d * 32 + lane] = make_uint2(pk(h0, h1), pk(h2, h3));
            ((uint2*)g_bufl)[(long)d * 32 + lane] = make_uint2(pk(l0, l1), pk(l2, l3));
        }
    }
}

// ---------------------------------------------------------------------------
// Finisher: one CTA per item, levels 4..7 + fused gather.
// ---------------------------------------------------------------------------
__global__ void __launch_bounds__(256, 4) k_finish(
    const float* __restrict__ b1, const float* __restrict__ b2,
    const float* __restrict__ lnw, const float* __restrict__ lnb,
    const int* __restrict__ lim, float* __restrict__ out)
{
    __shared__ __align__(16) unsigned char Xhi[16 * PITCHB];   // 8448 B
    __shared__ __align__(16) unsigned char Xlo[16 * PITCHB];

    int item = blockIdx.x;
    bool is64 = (lim[1] == 0);
    int L = get_limit(lim, is64, item + 1) - get_limit(lim, is64, item);
    int s = 0, l = L;
    #pragma unroll
    for (int t = 0; t < 4; t++) { int pr = l >> 1; s += 2 * pr; l = (l + 1) >> 1; }
    int rowb = item * RPI;

    uint32_t XhiA = smem_u32(Xhi);
    uint32_t XloA = smem_u32(Xlo);
    int tid = threadIdx.x;
    int warp = tid >> 5, lane = tid & 31;
    int lrow = lane & 15;
    int lcol = (lane >> 4) << 3;
    uint32_t rowA = (uint32_t)lrow * PITCHB;

    #pragma unroll 1
    for (int lev = 0; lev < 4 && l >= 2; lev++) {
        int pairs = l >> 1;    // 1..8

        {
            const uint4* sh = (const uint4*)g_bufh;
            const uint4* sl = (const uint4*)g_bufl;
            int tot = pairs * 32;
            for (int f = tid; f < tot; f += 256) {
                int r = f >> 5, q = f & 31;
                long gsrc = (long)(rowb + s + 2 * r) * 16 + q;
                *(uint4*)(Xhi + r * PITCHB + q * 16) = sh[gsrc];
                *(uint4*)(Xlo + r * PITCHB + q * 16) = sl[gsrc];
            }
        }
        __syncthreads();

        // GEMM1: warp tile 16 x 32
        float acc[4][4];
        #pragma unroll
        for (int nt = 0; nt < 4; nt++)
            #pragma unroll
            for (int e = 0; e < 4; e++) acc[nt][e] = 0.f;
        #pragma unroll 2
        for (int ks = 0; ks < 16; ks++) {
            uint32_t col2 = (uint32_t)(ks * 16 + lcol) * 2;
            uint32_t ah[4], al[4];
            ldm4(ah, XhiA + rowA + col2);
            ldm4(al, XloA + rowA + col2);
            #pragma unroll
            for (int nt = 0; nt < 4; nt++) {
                uint4 b = g_W1p[(ks * 32 + warp * 4 + nt) * 32 + lane];
                mma16816(acc[nt], ah, b.x, b.y);
                mma16816(acc[nt], ah, b.z, b.w);
                mma16816(acc[nt], al, b.x, b.y);
            }
        }
        __syncthreads();

        {
            int row = lane >> 2;
            #pragma unroll
            for (int nt = 0; nt < 4; nt++) {
                int col = (warp * 4 + nt) * 8 + (lane & 3) * 2;
                float v0 = fmaxf(acc[nt][0] + b1[col], 0.f);
                float v1 = fmaxf(acc[nt][1] + b1[col + 1], 0.f);
                float v2 = fmaxf(acc[nt][2] + b1[col], 0.f);
                float v3 = fmaxf(acc[nt][3] + b1[col + 1], 0.f);
                unsigned short h0, l0_, h1, l1_, h2, l2_, h3, l3_;
                split2(v0, h0, l0_); split2(v1, h1, l1_);
                split2(v2, h2, l2_); split2(v3, h3, l3_);
                *(uint32_t*)(Xhi + row * PITCHB + col * 2)       = pk(h0, h1);
                *(uint32_t*)(Xlo + row * PITCHB + col * 2)       = pk(l0_, l1_);
                *(uint32_t*)(Xhi + (row + 8) * PITCHB + col * 2) = pk(h2, h3);
                *(uint32_t*)(Xlo + (row + 8) * PITCHB + col * 2) = pk(l2_, l3_);
            }
        }
        __syncthreads();

        // GEMM2: warp tile 16 x 16
        float acc2[2][4];
        #pragma unroll
        for (int nt = 0; nt < 2; nt++)
            #pragma unroll
            for (int e = 0; e < 4; e++) acc2[nt][e] = 0.f;
        #pragma unroll 2
        for (int ks = 0; ks < 16; ks++) {
            uint32_t col2 = (uint32_t)(ks * 16 + lcol) * 2;
            uint32_t ah[4], al[4];
            ldm4(ah, XhiA + rowA + col2);
            ldm4(al, XloA + rowA + col2);
            #pragma unroll
            for (int nt = 0; nt < 2; nt++) {
                uint4 b = g_W2p[(ks * 16 + warp * 2 + nt) * 32 + lane];
                mma16816(acc2[nt], ah, b.x, b.y);
                mma16816(acc2[nt], ah, b.z, b.w);
                mma16816(acc2[nt], al, b.x, b.y);
            }
        }
        __syncthreads();

        float* Ys = (float*)Xhi;
        {
            int row = lane >> 2;
            #pragma unroll
            for (int nt = 0; nt < 2; nt++) {
                int col = (warp * 2 + nt) * 8 + (lane & 3) * 2;
                *(float2*)(Ys + row * 132 + col) =
                    make_float2(acc2[nt][0] + b2[col], acc2[nt][1] + b2[col + 1]);
                *(float2*)(Ys + (row + 8) * 132 + col) =
                    make_float2(acc2[nt][2] + b2[col], acc2[nt][3] + b2[col + 1]);
            }
        }
        __syncthreads();

        if (warp < pairs) {
            int row = warp;
            long d = rowb + s + l + row;
            float4 y = *(const float4*)(Ys + row * 132 + lane * 4);
            float sum = y.x + y.y + y.z + y.w;
            float sq  = y.x * y.x + y.y * y.y + y.z * y.z + y.w * y.w;
            #pragma unroll
            for (int o = 16; o > 0; o >>= 1) {
                sum += __shfl_xor_sync(0xFFFFFFFFu, sum, o);
                sq  += __shfl_xor_sync(0xFFFFFFFFu, sq, o);
            }
            float mu  = sum * (1.f / 128.f);
            float var = sq * (1.f / 128.f) - mu * mu;
            float rs  = rsqrtf(var + 1e-5f);
            float4 wv = ((const float4*)lnw)[lane];
            float4 bv = ((const float4*)lnb)[lane];
            float4 o;
            o.x = (y.x - mu) * rs * wv.x + bv.x;
            o.y = (y.y - mu) * rs * wv.y + bv.y;
            o.z = (y.z - mu) * rs * wv.z + bv.z;
            o.w = (y.w - mu) * rs * wv.w + bv.w;
            unsigned short h0, l0_, h1, l1_, h2, l2_, h3, l3_;
            split2(o.x, h0, l0_); split2(o.y, h1, l1_);
            split2(o.z, h2, l2_); split2(o.w, h3, l3_);
            ((uint2*)g_bufh)[d * 32 + lane] = make_uint2(pk(h0, h1), pk(h2, h3));
            ((uint2*)g_bufl)[d * 32 + lane] = make_uint2(pk(l0_, l1_), pk(l2_, l3_));
        }
        s += 2 * pairs;
        l = (l + 1) >> 1;
        __syncthreads();
    }

    // ---- Gather fused ----
    if (tid < DIM) {
        long idx = ((long)rowb + (2 * L - 2)) * DIM + tid;
        out[item * DIM + tid] =
            __bfloat162float(g_bufh[idx]) + __bfloat162float(g_bufl[idx]);
    }
}

// ---------------------------------------------------------------------------
extern "C" void kernel_launch(void* const* d_in, const int* in_sizes, int n_in,
                              void* d_out, int out_size) {
    const float* args = (const float*)d_in[0];
    const int*   lim  = (const int*)d_in[1];
    const float* W1   = (const float*)d_in[2];
    const float* b1   = (const float*)d_in[3];
    const float* W2   = (const float*)d_in[4];
    const float* b2   = (const float*)d_in[5];
    const float* lnw  = (const float*)d_in[6];
    const float* lnb  = (const float*)d_in[7];
    float* out = (float*)d_out;
    (void)n_in; (void)out_size;

    int T = in_sizes[0] / DIM;

    cudaFuncSetAttribute(k_level_mma, cudaFuncAttributeMaxDynamicSharedMemorySize, 2 * XBYTES);

    k_scan<<<1, NITEMS>>>(lim);
    k_fillw<<<NITEMS, 256>>>(lim, args, W1, W2);

    for (int k = 0; k < 4; k++) {
        int mp = (T >> (k + 1)) + NITEMS;
        int cap = NITEMS * (MAXM >> (k + 1));
        if (mp > cap) mp = cap;
        int ctas = (mp + TM - 1) / TM;
        k_level_mma<<<ctas, 256, 2 * XBYTES>>>(args, b1, b2, lnw, lnb, k);
    }
    k_finish<<<NITEMS, 256>>>(b1, b2, lnw, lnb, lim, out);
}